// round 5
// baseline (speedup 1.0000x reference)
#include <cuda_runtime.h>
#include <cuda_fp16.h>

#define IN_F  1024
#define OUT_F 1024
#define NG    8
#define BATCH 8192
#define K8    8192          // spline K (e4m3), k = i*8+g
#define KH    1024          // base K (fp16)

typedef unsigned int u32;
typedef unsigned short u16;
typedef unsigned long long u64;

// Device-global scratch (allocation-free contract)
__device__ unsigned char g_F8[(size_t)BATCH * K8];   // 67 MB e4m3, basis*16
__device__ unsigned char g_W8[(size_t)OUT_F * K8];   //  8 MB e4m3, w*ss*64
__device__ __half        g_Fh[(size_t)BATCH * KH];   // 17 MB fp16 silu
__device__ __half        g_Wb[(size_t)OUT_F * KH];   //  2 MB fp16 scale_base

// ============================================================================
// PTX helpers
// ============================================================================
__device__ __forceinline__ u32 smem_u32(const void* p) {
    u32 a;
    asm("{ .reg .u64 t; cvta.to.shared.u64 t, %1; cvt.u32.u64 %0, t; }" : "=r"(a) : "l"(p));
    return a;
}
#define CP_ASYNC16(sa, ga) \
    asm volatile("cp.async.cg.shared.global [%0], [%1], 16;" :: "r"(sa), "l"(ga))
#define CP_COMMIT() asm volatile("cp.async.commit_group;")
#define CP_WAIT2()  asm volatile("cp.async.wait_group 2;")

#define LDSM4(r, addr) \
    asm volatile("ldmatrix.sync.aligned.m8n8.x4.shared.b16 {%0,%1,%2,%3}, [%4];" \
                 : "=r"((r)[0]), "=r"((r)[1]), "=r"((r)[2]), "=r"((r)[3]) : "r"(addr))

#define MMA16816(d, a, b) \
    asm volatile("mma.sync.aligned.m16n8k16.row.col.f32.f16.f16.f32 " \
                 "{%0,%1,%2,%3}, {%4,%5,%6,%7}, {%8,%9}, {%0,%1,%2,%3};" \
                 : "+f"((d)[0]), "+f"((d)[1]), "+f"((d)[2]), "+f"((d)[3]) \
                 : "r"((a)[0]), "r"((a)[1]), "r"((a)[2]), "r"((a)[3]), \
                   "r"((b)[0]), "r"((b)[1]))

#define MMA16832F8(d, a, b) \
    asm volatile("mma.sync.aligned.m16n8k32.row.col.f32.e4m3.e4m3.f32 " \
                 "{%0,%1,%2,%3}, {%4,%5,%6,%7}, {%8,%9}, {%0,%1,%2,%3};" \
                 : "+f"((d)[0]), "+f"((d)[1]), "+f"((d)[2]), "+f"((d)[3]) \
                 : "r"((a)[0]), "r"((a)[1]), "r"((a)[2]), "r"((a)[3]), \
                   "r"((b)[0]), "r"((b)[1]))

__device__ __forceinline__ u16 cvt2_e4m3(float lo, float hi) {
    u16 r;
    asm("cvt.rn.satfinite.e4m3x2.f32 %0, %1, %2;" : "=h"(r) : "f"(hi), "f"(lo));
    return r;
}

// ============================================================================
// Phase A: weights. W8[o][i*8+g] = spline_w[o][i][g]*ss*64 ; Wb[o][i] = sb
// ============================================================================
__global__ void build_w_kernel(const float* __restrict__ scale_base,
                               const float* __restrict__ spline_weight,
                               const float* __restrict__ scale_spline) {
    int idx = blockIdx.x * blockDim.x + threadIdx.x;
    if (idx >= IN_F * OUT_F) return;
    int o = idx >> 10;
    int i = idx & 1023;

    float sb = scale_base[(size_t)i * OUT_F + o];
    float ss = scale_spline[(size_t)i * OUT_F + o] * 64.0f;
    g_Wb[(size_t)o * KH + i] = __float2half_rn(sb);

    const float4* swp = reinterpret_cast<const float4*>(spline_weight + ((size_t)o * IN_F + i) * NG);
    float4 w0 = swp[0];
    float4 w1 = swp[1];
    u64 pk = (u64)cvt2_e4m3(w0.x * ss, w0.y * ss)
           | ((u64)cvt2_e4m3(w0.z * ss, w0.w * ss) << 16)
           | ((u64)cvt2_e4m3(w1.x * ss, w1.y * ss) << 32)
           | ((u64)cvt2_e4m3(w1.z * ss, w1.w * ss) << 48);
    *(u64*)(g_W8 + (size_t)o * K8 + (size_t)i * 8) = pk;
}

// ============================================================================
// Phase B: features. F8[b][i*8+g] = 16*exp(-t^2) ; Fh[b][i] = silu(x)
// ============================================================================
__global__ void build_f_kernel(const float* __restrict__ x,
                               const float* __restrict__ grid,
                               const float* __restrict__ sigma_p) {
    int idx = blockIdx.x * blockDim.x + threadIdx.x;
    if (idx >= BATCH * IN_F) return;
    int b = idx >> 10;
    int i = idx & (IN_F - 1);

    float xv = x[idx];
    float inv_sigma = __fdividef(1.0f, *sigma_p);

    g_Fh[(size_t)b * KH + i] = __float2half_rn(__fdividef(xv, 1.0f + __expf(-xv)));

    const float4* gp = reinterpret_cast<const float4*>(grid + (size_t)i * NG);
    float4 g0 = gp[0];
    float4 g1 = gp[1];
    float gv[NG] = {g0.x, g0.y, g0.z, g0.w, g1.x, g1.y, g1.z, g1.w};
    float bs[NG];
#pragma unroll
    for (int g = 0; g < NG; g++) {
        float t = (xv - gv[g]) * inv_sigma;
        bs[g] = 16.0f * __expf(-t * t);
    }
    u64 pk = (u64)cvt2_e4m3(bs[0], bs[1])
           | ((u64)cvt2_e4m3(bs[2], bs[3]) << 16)
           | ((u64)cvt2_e4m3(bs[4], bs[5]) << 32)
           | ((u64)cvt2_e4m3(bs[6], bs[7]) << 48);
    *(u64*)(g_F8 + (size_t)b * K8 + (size_t)i * 8) = pk;
}

// ============================================================================
// Phase C: mixed fp8/fp16 GEMM.
//   64 fp8 tiles (BK=128B) then 16 fp16 tiles (BK=64 halves = 128B).
//   BM=128 BN=128, 4-stage cp.async (32KB/stage), 8 warps 2Mx4N, warp 64x32.
// ============================================================================
#define BM 128
#define BN 128
#define NT8 64                     // spline tiles
#define NTH 16                     // base tiles
#define NT  (NT8 + NTH)            // 80
#define STG_A 16384                // 128 rows x 128B
#define STG_B 16384
#define STG_BYTES (STG_A + STG_B)
#define SMEM_TOTAL (4 * STG_BYTES) // 131072

// load one tile into stage (kt&3). Both phases: 128 rows x 128B per operand.
__device__ __forceinline__ void load_tile(u32 sbase, int brow, int bcol, int kt,
                                          int lr, int lc, u32 phys) {
    const u32 sA = sbase + (u32)(kt & 3) * STG_BYTES;
    const u32 sB = sA + STG_A;
    if (kt < NT8) {
        const unsigned char* ga = g_F8 + (size_t)(brow + lr) * K8 + (size_t)kt * 128 + lc * 16;
        const unsigned char* gb = g_W8 + (size_t)(bcol + lr) * K8 + (size_t)kt * 128 + lc * 16;
#pragma unroll
        for (int it = 0; it < 4; it++) {
            u32 off = (u32)(lr + 32 * it) * 128 + phys;
            CP_ASYNC16(sA + off, ga + (size_t)(32 * it) * K8);
            CP_ASYNC16(sB + off, gb + (size_t)(32 * it) * K8);
        }
    } else {
        const int kh = kt - NT8;
        const __half* ga = g_Fh + (size_t)(brow + lr) * KH + (size_t)kh * 64 + lc * 8;
        const __half* gb = g_Wb + (size_t)(bcol + lr) * KH + (size_t)kh * 64 + lc * 8;
#pragma unroll
        for (int it = 0; it < 4; it++) {
            u32 off = (u32)(lr + 32 * it) * 128 + phys;
            CP_ASYNC16(sA + off, ga + (size_t)(32 * it) * KH);
            CP_ASYNC16(sB + off, gb + (size_t)(32 * it) * KH);
        }
    }
    CP_COMMIT();
}

__global__ void __launch_bounds__(256, 1)
gemm_kernel(float* __restrict__ C) {
    extern __shared__ __align__(1024) char smem[];
    const u32 sbase = smem_u32(smem);
    const int tid = threadIdx.x;
    const int lane = tid & 31;
    const int wid = tid >> 5;
    const int wm = wid & 1;
    const int wn = wid >> 1;
    const int brow = blockIdx.y * BM;
    const int bcol = blockIdx.x * BN;

    const int lr = tid >> 3;
    const int lc = tid & 7;
    const u32 phys = (u32)((lc ^ (lr & 7)) << 4);

    float acc[4][4][4];
#pragma unroll
    for (int mi = 0; mi < 4; mi++)
#pragma unroll
        for (int ni = 0; ni < 4; ni++)
#pragma unroll
            for (int q = 0; q < 4; q++) acc[mi][ni][q] = 0.0f;

    load_tile(sbase, brow, bcol, 0, lr, lc, phys);
    load_tile(sbase, brow, bcol, 1, lr, lc, phys);
    load_tile(sbase, brow, bcol, 2, lr, lc, phys);

    const int j = lane >> 3;
    const int i8 = lane & 7;
    const int arow_in = (j & 1) * 8 + i8;
    const int nrow_in = (j >> 1) * 8 + i8;

    // ---- phase 1: fp8 spline tiles ----
    for (int kt = 0; kt < NT8; kt++) {
        CP_WAIT2();
        __syncthreads();
        if (kt + 3 < NT) load_tile(sbase, brow, bcol, kt + 3, lr, lc, phys);
        const u32 sA = sbase + (u32)(kt & 3) * STG_BYTES;
        const u32 sB = sA + STG_A;
#pragma unroll
        for (int ks = 0; ks < 4; ks++) {
            u32 a[4][4], b[4][2];
            const int cA = ks * 2 + (j >> 1);
            const int cB = ks * 2 + (j & 1);
#pragma unroll
            for (int mi = 0; mi < 4; mi++) {
                int ar = wm * 64 + mi * 16 + arow_in;
                LDSM4(a[mi], sA + (u32)ar * 128 + (u32)((cA ^ i8) << 4));
            }
#pragma unroll
            for (int p = 0; p < 2; p++) {
                int br = wn * 32 + p * 16 + nrow_in;
                u32 r[4];
                LDSM4(r, sB + (u32)br * 128 + (u32)((cB ^ i8) << 4));
                b[2 * p][0] = r[0];     b[2 * p][1] = r[1];
                b[2 * p + 1][0] = r[2]; b[2 * p + 1][1] = r[3];
            }
#pragma unroll
            for (int mi = 0; mi < 4; mi++)
#pragma unroll
                for (int ni = 0; ni < 4; ni++)
                    MMA16832F8(acc[mi][ni], a[mi], b[ni]);
        }
    }

    // descale spline accumulation (F8 *16, W8 *64)
#pragma unroll
    for (int mi = 0; mi < 4; mi++)
#pragma unroll
        for (int ni = 0; ni < 4; ni++)
#pragma unroll
            for (int q = 0; q < 4; q++) acc[mi][ni][q] *= (1.0f / 1024.0f);

    // ---- phase 2: fp16 base tiles ----
    for (int kt = NT8; kt < NT; kt++) {
        CP_WAIT2();
        __syncthreads();
        if (kt + 3 < NT) load_tile(sbase, brow, bcol, kt + 3, lr, lc, phys);
        const u32 sA = sbase + (u32)(kt & 3) * STG_BYTES;
        const u32 sB = sA + STG_A;
#pragma unroll
        for (int ks = 0; ks < 4; ks++) {
            u32 a[4][4], b[4][2];
            const int cA = ks * 2 + (j >> 1);
            const int cB = ks * 2 + (j & 1);
#pragma unroll
            for (int mi = 0; mi < 4; mi++) {
                int ar = wm * 64 + mi * 16 + arow_in;
                LDSM4(a[mi], sA + (u32)ar * 128 + (u32)((cA ^ i8) << 4));
            }
#pragma unroll
            for (int p = 0; p < 2; p++) {
                int br = wn * 32 + p * 16 + nrow_in;
                u32 r[4];
                LDSM4(r, sB + (u32)br * 128 + (u32)((cB ^ i8) << 4));
                b[2 * p][0] = r[0];     b[2 * p][1] = r[1];
                b[2 * p + 1][0] = r[2]; b[2 * p + 1][1] = r[3];
            }
#pragma unroll
            for (int mi = 0; mi < 4; mi++)
#pragma unroll
                for (int ni = 0; ni < 4; ni++)
                    MMA16816(acc[mi][ni], a[mi], b[ni]);
        }
    }

    // epilogue
    const int r0 = brow + wm * 64 + (lane >> 2);
    const int c0 = bcol + wn * 32 + 2 * (lane & 3);
#pragma unroll
    for (int mi = 0; mi < 4; mi++) {
#pragma unroll
        for (int ni = 0; ni < 4; ni++) {
            float* p = C + (size_t)(r0 + mi * 16) * OUT_F + c0 + ni * 8;
            *(float2*)p = make_float2(acc[mi][ni][0], acc[mi][ni][1]);
            *(float2*)(p + (size_t)8 * OUT_F) = make_float2(acc[mi][ni][2], acc[mi][ni][3]);
        }
    }
}

// ============================================================================
extern "C" void kernel_launch(void* const* d_in, const int* in_sizes, int n_in,
                              void* d_out, int out_size) {
    const float* x             = (const float*)d_in[0];
    const float* scale_base    = (const float*)d_in[1];
    const float* spline_weight = (const float*)d_in[2];
    const float* scale_spline  = (const float*)d_in[3];
    const float* grid          = (const float*)d_in[4];
    const float* sigma         = (const float*)d_in[5];
    float* out = (float*)d_out;

    static bool attr_set = false;
    if (!attr_set) {
        cudaFuncSetAttribute(gemm_kernel,
                             cudaFuncAttributeMaxDynamicSharedMemorySize, SMEM_TOTAL);
        attr_set = true;
    }

    build_w_kernel<<<(IN_F * OUT_F + 255) / 256, 256>>>(scale_base, spline_weight, scale_spline);
    build_f_kernel<<<(BATCH * IN_F + 255) / 256, 256>>>(x, grid, sigma);
    gemm_kernel<<<dim3(OUT_F / BN, BATCH / BM), 256, SMEM_TOTAL>>>(out);
}